// round 9
// baseline (speedup 1.0000x reference)
#include <cuda_runtime.h>
#include <math.h>

#define NBOX 8192
#define LCLS 8
#define CAP   1536         // total per-label capacity
#define NBUCK 4
#define BCAP  384          // per-bucket capacity (mean 256, +9.3 sigma)
#define NT    128
#define NW    (NT / 32)
#define MAXK  12           // BCAP / 32
#define FULLMASK 0xffffffffu

// Scratch (no allocations allowed): per-label keep lists + counts.
__device__ int d_keep[LCLS * CAP];
__device__ int d_kc[LCLS];

// ---------------------------------------------------------------------------
// float-float exp(x) for x in (-2, 0], FFMA-only hot path (validated bit-exact
// vs jax f32 exp in R3/R6/R7: rel_err 0.0).
// ---------------------------------------------------------------------------
__device__ __forceinline__ float exp_ff(float x, const float2* __restrict__ tab,
                                        float L2c, float L3c)
{
    const float I   = 738.66585811433f;   // 512/ln2
    const float L1c = 0x1.62ep-10f;       // 13-bit head of ln2/512 (n*L1 exact)

    float nf = rintf(x * I);
    int   n  = (int)nf;
    float a  = fmaf(-nf, L1c, x);         // exact
    float t  = nf * L2c;
    float b   = -t;
    float rh  = a + b;
    float bb  = rh - a;
    float err = (a - (rh - bb)) + (b - bb);
    float dt  = fmaf(nf, L2c, -t);        // exact rounding residual of t
    float rl  = err - dt - nf * L3c;
    float q = fmaf(rh, 0.041666668f, 0.16666667f);
    q       = fmaf(rh, q, 0.5f);
    float s = (rh * rh) * q;
    float uh  = 1.0f + rh;
    float ul  = rh - (uh - 1.0f);
    float low = (ul + rl) + s;
    float mh  = uh + low;
    float ml  = low - (mh - uh);
    int e = n >> 9;
    int k = n - (e << 9);
    float2 T = tab[k];
    float ph = T.x * mh;
    float pl = fmaf(T.x, mh, -ph);        // exact
    pl = fmaf(T.x, ml, pl);
    pl = fmaf(T.y, mh, pl);
    float se = __int_as_float((127 + e) << 23);   // 2^e, e in [-3,0]
    return fmaf(ph, se, pl * se);
}

__global__ __launch_bounds__(NT, 1)
void softnms_kernel(const float4* __restrict__ boxes,
                    const float* __restrict__ scores,
                    const int* __restrict__ labels)
{
    const int l    = blockIdx.x;
    const int t    = threadIdx.x;
    const int warp = t >> 5;
    const int lane = t & 31;

    __shared__ float4   sBox[CAP];        // by storage position (bucketed)
    __shared__ float    sSc[CAP];         // by storage position
    __shared__ int      sPO[CAP];         // storage -> original compacted position
    __shared__ int      sOrd[CAP];        // original position -> global box index
    __shared__ float2   sTab[512];
    __shared__ float    sL2c, sL3c;
    __shared__ int      sWCnt[NW];
    __shared__ int      bCnt[NBUCK];
    __shared__ uint4    bPost[2][NW];     // {key, storagePos, rankPart, pOrig}
    __shared__ int      sBase;

    // ---------------- one-time prologue: exp table + constants ----------------
    for (int q = t; q < 512; q += NT) {
        double v = exp2((double)q * (1.0 / 512.0));
        float hi = (float)v;
        sTab[q] = make_float2(hi, (float)(v - (double)hi));
    }
    if (t == 0) {
        double Ld = 0.69314718055994530941723212145818 / 512.0;
        const float L1c = 0x1.62ep-10f;
        float l2 = (float)(Ld - (double)L1c);
        sL2c = l2;
        sL3c = (float)(Ld - (double)L1c - (double)l2);
        sBase = 0;
    }
    if (t < NBUCK) bCnt[t] = 0;
    __syncthreads();

    // ------- stable per-label compaction (pOrig order) + x-bucket scatter -----
    for (int start = 0; start < NBOX; start += NT) {
        const int j = start + t;
        const bool flag = (labels[j] == l);
        const unsigned ball = __ballot_sync(FULLMASK, flag);
        const int wpre = __popc(ball & ((1u << lane) - 1u));
        if (lane == 0) sWCnt[warp] = __popc(ball);
        __syncthreads();
        int pre = 0, tot = 0;
#pragma unroll
        for (int w = 0; w < NW; w++) {
            const int c = sWCnt[w];
            if (w < warp) pre += c;
            tot += c;
        }
        if (flag) {
            const int p = sBase + pre + wpre;   // original compacted position
            if (p < CAP) {
                sOrd[p] = j;
                const float4 bb = boxes[j];
                int b = (int)(bb.x * 0.004f);   // x1 in [0,1000) -> 4 strips
                b = max(0, min(NBUCK - 1, b));
                const int idx = atomicAdd(&bCnt[b], 1);
                if (idx < BCAP) {
                    const int st = b * BCAP + idx;
                    sBox[st] = bb;
                    sSc[st]  = scores[j];
                    sPO[st]  = p;
                }
            }
        }
        __syncthreads();
        if (t == 0) sBase += tot;
        __syncthreads();
    }

    const int cnt = min(bCnt[warp], BCAP);     // my bucket's element count
    const int Kw  = (cnt + 31) >> 5;           // my slots
    const float L2c = sL2c, L3c = sL3c;

    // Per-lane register-resident working set (strided within bucket)
    float ws[MAXK], ax[MAXK], ay[MAXK], bx[MAXK], by[MAXK], area[MAXK];
    int   po[MAXK];
#pragma unroll
    for (int k = 0; k < MAXK; k++) {
        const int e  = (k << 5) + lane;
        const bool v = (k < Kw) && (e < cnt);
        const int st = warp * BCAP + e;
        ws[k] = v ? sSc[st] : -1.0f;
        po[k] = v ? sPO[st] : 0x7fffffff;
        const float4 bb = v ? sBox[st] : make_float4(0.f, 0.f, 0.f, 0.f);
        ax[k] = bb.x; ay[k] = bb.y; bx[k] = bb.z; by[k] = bb.w;
        area[k] = (bb.z - bb.x) * (bb.w - bb.y);
    }

    // ---------------- initial scan -> post {key, stor, 0, pOrig} --------------
    {
        unsigned lkey = 0u, lst = 0u;
        int lpo = 0x7fffffff;
#pragma unroll
        for (int k = 0; k < MAXK; k++) {
            if (k >= Kw) break;
            const float sc = ws[k];
            if (sc >= 0.0f) {
                const unsigned b = __float_as_uint(sc);
                if (b > lkey || (b == lkey && po[k] < lpo)) {
                    lkey = b; lpo = po[k];
                    lst = (unsigned)(warp * BCAP + (k << 5) + lane);
                }
            }
        }
        const unsigned wkey = __reduce_max_sync(FULLMASK, lkey);
        const int cpo  = (lkey == wkey) ? lpo : 0x7fffffff;
        const int wpo  = __reduce_min_sync(FULLMASK, cpo);
        const unsigned ball = __ballot_sync(FULLMASK, (lkey == wkey) && (lpo == wpo));
        const int wl = __ffs(ball) - 1;
        const unsigned wst = __shfl_sync(FULLMASK, lst, wl);
        if (lane == 0) bPost[0][warp] = make_uint4(wkey, wst, 0u, (unsigned)wpo);
    }
    __syncthreads();

    // ---------------- sequential Soft-NMS loop -------------------------------
    const float wlo = 250.0f * warp;
    const float whi = wlo + 250.0f + 130.0f;   // strip hi + max box width margin
    int kc = 0, cur = 0;
    for (;;) {
        // combine 4 warp posts; tie -> min pOrig (exact jnp.argmax)
        unsigned bk = 0u, bst = 0u;
        int bpo = 0x7fffffff, rsum = 0;
#pragma unroll
        for (int w = 0; w < NW; w++) {
            const uint4 v = bPost[cur][w];
            rsum += (int)v.z;
            if (v.x > bk || (v.x == bk && (int)v.w < bpo)) {
                bk = v.x; bst = v.y; bpo = (int)v.w;
            }
        }
        // deferred keep-write for the PREVIOUS selection (off critical path)
        if (kc > 0 && t == 0) d_keep[l * CAP + (kc - 1)] = sOrd[rsum];
        if (bk == 0u) break;
        kc++;
        const int pSel = bpo;
        const float4 sb = sBox[bst];           // broadcast LDS

        // whole-warp spatial skip: can any of my strip's boxes overlap sel in x?
        const bool activeW = !((whi <= sb.x) || (wlo >= sb.z));
        unsigned nkey = 0u, nst = 0u;
        int npo = 0x7fffffff, rloc = 0;
        if (activeW) {
            const float aS = (sb.z - sb.x) * (sb.w - sb.y);
#pragma unroll
            for (int k = 0; k < MAXK; k++) {
                if (k >= Kw) break;
                const float sc = ws[k];
                const bool alive = (sc >= 0.0f);
                const int pk = po[k];
                rloc += (alive & (pk < pSel)) ? 1 : 0;   // rank vs pre-decay set
                const float lx = fmaxf(sb.x, ax[k]);
                const float ly = fmaxf(sb.y, ay[k]);
                const float rx = fminf(sb.z, bx[k]);
                const float ry = fminf(sb.w, by[k]);
                const float inter = fmaxf(rx - lx, 0.0f) * fmaxf(ry - ly, 0.0f);
                const bool hot = alive & (inter > 0.0f) & (pk != pSel);
                float nv = sc;
                if (hot) {                     // rare {div, exp} region
                    const float iou = inter / (aS + area[k] - inter + 1e-8f);
                    const float arg = -(iou * iou) * 2.0f;
                    nv = sc * exp_ff(arg, sTab, L2c, L3c);
                }
                // SCORE_THR re-applied to ALL alive boxes every iteration
                const bool keep = (nv >= 0.001f) & (pk != pSel);
                ws[k] = keep ? nv : -1.0f;
                const unsigned b = keep ? __float_as_uint(nv) : 0u;
                if (b > nkey || (b == nkey && pk < npo)) {
                    nkey = b; npo = pk;
                    nst = (unsigned)(warp * BCAP + (k << 5) + lane);
                }
            }
        } else {
            // spatially skipped: no decay possible, but the reference still
            // re-applies SCORE_THR to every alive box each iteration — do the
            // kill + rank + argmax recompute (no IoU/div/exp). This also makes
            // the post always fresh (no cached-state staleness).
#pragma unroll
            for (int k = 0; k < MAXK; k++) {
                if (k >= Kw) break;
                const float sc = ws[k];
                const bool alive = (sc >= 0.0f);
                const int pk = po[k];
                rloc += (alive & (pk < pSel)) ? 1 : 0;
                const bool keep = (sc >= 0.001f);      // pSel never in this warp
                ws[k] = keep ? sc : -1.0f;
                const unsigned b = keep ? __float_as_uint(sc) : 0u;
                if (b > nkey || (b == nkey && pk < npo)) {
                    nkey = b; npo = pk;
                    nst = (unsigned)(warp * BCAP + (k << 5) + lane);
                }
            }
        }
        // warp argmax (short chain) + independent rank reduce (overlapped)
        const unsigned wkey = __reduce_max_sync(FULLMASK, nkey);
        const int cpo = (nkey == wkey) ? npo : 0x7fffffff;
        const int wpo = __reduce_min_sync(FULLMASK, cpo);
        const unsigned ball = __ballot_sync(FULLMASK, (nkey == wkey) && (npo == wpo));
        const int wl = __ffs(ball) - 1;
        const unsigned wst = __shfl_sync(FULLMASK, nst, wl);
        const int wrank = __reduce_add_sync(FULLMASK, rloc);
        if (lane == 0) bPost[cur ^ 1][warp] = make_uint4(wkey, wst, (unsigned)wrank, (unsigned)wpo);
        __syncthreads();
        cur ^= 1;
    }

    if (t == 0) d_kc[l] = kc;
}

// ---------------- gather + pack outputs ----------------
// Layout (float32): boxes[N*4] | scores[N] | labels[N] | count[1]
__global__ void gather_kernel(const float4* __restrict__ boxes,
                              const float* __restrict__ scores,
                              const int* __restrict__ labels,
                              float* __restrict__ out)
{
    const int j = blockIdx.x * blockDim.x + threadIdx.x;

    int off[LCLS + 1];
    off[0] = 0;
#pragma unroll
    for (int l = 0; l < LCLS; l++) off[l + 1] = off[l] + d_kc[l];
    const int total = off[LCLS];

    if (j == 0) out[NBOX * 6] = (float)total;
    if (j >= NBOX) return;

    float4 b = make_float4(0.f, 0.f, 0.f, 0.f);
    float s = 0.f, lab = 0.f;
    if (j < total) {
        int l = 0;
#pragma unroll
        for (int q = 1; q < LCLS; q++) if (j >= off[q]) l = q;
        const int g = d_keep[l * CAP + (j - off[l])];
        b = boxes[g];
        s = scores[g];
        lab = (float)labels[g];
    }
    reinterpret_cast<float4*>(out)[j] = b;
    out[NBOX * 4 + j] = s;
    out[NBOX * 5 + j] = lab;
}

extern "C" void kernel_launch(void* const* d_in, const int* in_sizes, int n_in,
                              void* d_out, int out_size)
{
    const float4* boxes  = (const float4*)d_in[0];
    const float*  scores = (const float*)d_in[1];
    const int*    labels = (const int*)d_in[2];
    float* out = (float*)d_out;

    softnms_kernel<<<LCLS, NT>>>(boxes, scores, labels);
    gather_kernel<<<NBOX / NT, NT>>>(boxes, scores, labels, out);
}